// round 15
// baseline (speedup 1.0000x reference)
#include <cuda_runtime.h>
#include <cuda_bf16.h>
#include <cstdint>

#define DIM   1024
#define CANDN 16384
#define SSZ   512
#define MSZ   4096
#define LSZ   8192
#define KPROM 128
#define PD    64
#define PAIR_CAP 65536
#define NLCHUNK 128
#define NVCHUNK 64
#define TB   128
#define NBT  32
#define NTRI (NBT*(NBT+1)/2)
#define LDPB 72
#define COLLECT_CAP 2048
#define SCREEN_T 0.974f
#define MERGE_T  0.98f

// block partition of k_stream
#define NB_LMEAN 512
#define NB_TOK   2048
#define NB_MPREP 512
#define NB_COPY  1536
#define NB_TOTAL (NB_LMEAN + NB_TOK + NB_MPREP + NB_COPY)

// ------------- scratch -------------
__device__ float g_norms[CANDN];
__device__ int   g_top[KPROM];
__device__ float g_lpart[NLCHUNK * DIM];
__device__ float g_mean[DIM];
__device__ float g_q[DIM];
__device__ float g_vpart[NVCHUNK * DIM];
__device__ float g_scores[SSZ];
__device__ float g_cand[DIM];
__device__ float g_candn2;
__device__ float g_mn2[MSZ];
__device__ float g_sims[MSZ];
__device__ __nv_bfloat16 g_Pb[MSZ * PD];
__device__ float g_res[MSZ];
__device__ int   g_pairs[PAIR_CAP * 2];
__device__ int   g_npairs;
__device__ unsigned long long g_intmax;

// ------------- helpers -------------
__device__ __forceinline__ float dot4(float4 a, float4 b) {
    return a.x*b.x + a.y*b.y + a.z*b.z + a.w*b.w;
}
__device__ __forceinline__ float wsum(float v) {
#pragma unroll
    for (int o = 16; o; o >>= 1) v += __shfl_xor_sync(0xFFFFFFFFu, v, o);
    return v;
}
__device__ __forceinline__ unsigned ordf(float f) {
    unsigned u = __float_as_uint(f);
    return (u & 0x80000000u) ? ~u : (u | 0x80000000u);
}
__device__ __forceinline__ float deordf(unsigned u) {
    return (u & 0x80000000u) ? __uint_as_float(u & 0x7FFFFFFFu) : __uint_as_float(~u);
}
__device__ __forceinline__ float bsum(float v, float* sbuf) {
    int t = threadIdx.x, lane = t & 31, wid = t >> 5;
    v = wsum(v);
    if (!lane) sbuf[wid] = v;
    __syncthreads();
    int nw = blockDim.x >> 5;
    if (wid == 0) {
        float x = (lane < nw) ? sbuf[lane] : 0.f;
        x = wsum(x);
        if (!lane) sbuf[0] = x;
    }
    __syncthreads();
    v = sbuf[0];
    __syncthreads();
    return v;
}
__device__ __forceinline__ void bargmax(float& bv, int& bi, float* sv, int* si) {
    int t = threadIdx.x, lane = t & 31, wid = t >> 5;
#pragma unroll
    for (int o = 16; o; o >>= 1) {
        float ov = __shfl_xor_sync(0xFFFFFFFFu, bv, o);
        int   oi = __shfl_xor_sync(0xFFFFFFFFu, bi, o);
        if (ov > bv || (ov == bv && oi < bi)) { bv = ov; bi = oi; }
    }
    if (!lane) { sv[wid] = bv; si[wid] = bi; }
    __syncthreads();
    int nw = blockDim.x >> 5;
    if (wid == 0) {
        float xv = (lane < nw) ? sv[lane] : -3e38f;
        int   xi = (lane < nw) ? si[lane] : 0x7FFFFFFF;
#pragma unroll
        for (int o = 16; o; o >>= 1) {
            float ov = __shfl_xor_sync(0xFFFFFFFFu, xv, o);
            int   oi = __shfl_xor_sync(0xFFFFFFFFu, xi, o);
            if (ov > xv || (ov == xv && oi < xi)) { xv = ov; xi = oi; }
        }
        if (!lane) { sv[0] = xv; si[0] = xi; }
    }
    __syncthreads();
    bv = sv[0]; bi = si[0];
    __syncthreads();
}
__device__ __forceinline__ void bargmin(float& bv, int& bi, float* sv, int* si) {
    int t = threadIdx.x, lane = t & 31, wid = t >> 5;
#pragma unroll
    for (int o = 16; o; o >>= 1) {
        float ov = __shfl_xor_sync(0xFFFFFFFFu, bv, o);
        int   oi = __shfl_xor_sync(0xFFFFFFFFu, bi, o);
        if (ov < bv || (ov == bv && oi < bi)) { bv = ov; bi = oi; }
    }
    if (!lane) { sv[wid] = bv; si[wid] = bi; }
    __syncthreads();
    int nw = blockDim.x >> 5;
    if (wid == 0) {
        float xv = (lane < nw) ? sv[lane] : 3e38f;
        int   xi = (lane < nw) ? si[lane] : 0x7FFFFFFF;
#pragma unroll
        for (int o = 16; o; o >>= 1) {
            float ov = __shfl_xor_sync(0xFFFFFFFFu, xv, o);
            int   oi = __shfl_xor_sync(0xFFFFFFFFu, xi, o);
            if (ov < xv || (ov == xv && oi < xi)) { xv = ov; xi = oi; }
        }
        if (!lane) { sv[0] = xv; si[0] = xi; }
    }
    __syncthreads();
    bv = sv[0]; bi = si[0];
    __syncthreads();
}

__device__ __forceinline__ void ldsm4(uint32_t addr, uint32_t& r0, uint32_t& r1,
                                      uint32_t& r2, uint32_t& r3) {
    asm volatile("ldmatrix.sync.aligned.m8n8.x4.shared.b16 {%0,%1,%2,%3}, [%4];"
                 : "=r"(r0), "=r"(r1), "=r"(r2), "=r"(r3) : "r"(addr));
}
__device__ __forceinline__ void ldsm2(uint32_t addr, uint32_t& r0, uint32_t& r1) {
    asm volatile("ldmatrix.sync.aligned.m8n8.x2.shared.b16 {%0,%1}, [%2];"
                 : "=r"(r0), "=r"(r1) : "r"(addr));
}
__device__ __forceinline__ void mma16816(float& c0, float& c1, float& c2, float& c3,
                                         uint32_t a0, uint32_t a1, uint32_t a2, uint32_t a3,
                                         uint32_t b0, uint32_t b1) {
    asm volatile("mma.sync.aligned.m16n8k16.row.col.f32.bf16.bf16.f32 "
                 "{%0,%1,%2,%3}, {%4,%5,%6,%7}, {%8,%9}, {%0,%1,%2,%3};"
                 : "+f"(c0), "+f"(c1), "+f"(c2), "+f"(c3)
                 : "r"(a0), "r"(a1), "r"(a2), "r"(a3), "r"(b0), "r"(b1));
}

__device__ __forceinline__ const float* srow(int i, int sp,
                                             const float* __restrict__ tok,
                                             const float* __restrict__ s_in) {
    int d = ((i - sp) % SSZ + SSZ) % SSZ;
    if (d < KPROM) return tok + (size_t)g_top[d] * DIM;
    return s_in + (size_t)i * DIM;
}

// ------------- kernels -------------

// streaming megakernel: lmean | toknorm | mprep | copies (+ zero g_mean, flags)
__global__ void __launch_bounds__(256) k_stream(
    const float* __restrict__ tok, const float* __restrict__ m,
    const float* __restrict__ l_in, float* __restrict__ out_l,
    const float4* __restrict__ s_in4, float4* __restrict__ out_s4,
    const float4* __restrict__ m4, float4* __restrict__ out_m4,
    const float4* __restrict__ mu4, float4* __restrict__ out_mu4,
    const float4* __restrict__ lu4, float4* __restrict__ out_lu4)
{
    int b = blockIdx.x, t = threadIdx.x;
    if (b == 0 && t == 0) { g_npairs = 0; g_intmax = 0ull; }
    // zero g_mean for the atomic reduction in k_lred (4 copy-section blocks)
    if (b >= NB_LMEAN + NB_TOK + NB_MPREP && b < NB_LMEAN + NB_TOK + NB_MPREP + 4)
        g_mean[(b - NB_LMEAN - NB_TOK - NB_MPREP) * 256 + t] = 0.f;

    if (b < NB_LMEAN) {
        int c  = (b & 3) * 256 + t;
        int r0 = (b >> 2) * (LSZ / NLCHUNK);
        float s = 0.f;
#pragma unroll 4
        for (int r = r0; r < r0 + (LSZ / NLCHUNK); r++) {
            float v = l_in[(size_t)r * DIM + c];
            out_l[(size_t)r * DIM + c] = v;
            s += v;
        }
        g_lpart[(b >> 2) * DIM + c] = s;
    } else if (b < NB_LMEAN + NB_TOK) {
        int w = ((b - NB_LMEAN) * 256 + t) >> 5;
        int lane = t & 31;
        const float4* p = (const float4*)(tok + (size_t)w * DIM);
        float s = 0.f;
#pragma unroll
        for (int k = 0; k < 8; k++) { float4 v = p[lane + 32 * k]; s += dot4(v, v); }
        s = wsum(s);
        if (!lane) g_norms[w] = s;
    } else if (b < NB_LMEAN + NB_TOK + NB_MPREP) {
        int w = ((b - NB_LMEAN - NB_TOK) * 256 + t) >> 5;
        int lane = t & 31;
        const float4* mr = (const float4*)(m + (size_t)w * DIM);
        float n2 = 0.f;
        float4 v0 = make_float4(0, 0, 0, 0);
#pragma unroll
        for (int k = 0; k < 8; k++) {
            float4 v = mr[lane + 32 * k];
            n2 += dot4(v, v);
            if (k == 0) v0 = v;
        }
        n2 = wsum(n2);
        float sp2 = (lane < 16) ? dot4(v0, v0) : 0.f;
        sp2 = wsum(sp2);
        float rinv = rsqrtf(n2);
        if (lane < 16) {
            __nv_bfloat162 lo = __floats2bfloat162_rn(v0.x * rinv, v0.y * rinv);
            __nv_bfloat162 hi = __floats2bfloat162_rn(v0.z * rinv, v0.w * rinv);
            __nv_bfloat162* dst = (__nv_bfloat162*)(g_Pb + (size_t)w * PD + lane * 4);
            dst[0] = lo;
            dst[1] = hi;
        }
        if (!lane) {
            g_mn2[w] = n2;
            g_res[w] = sqrtf(fmaxf(0.f, 1.f - sp2 * rinv * rinv));
        }
    } else {
        const int nS = SSZ * DIM / 4, nM = MSZ * DIM / 4, nMu = MSZ / 4, nLu = LSZ / 4;
        int i = (b - NB_LMEAN - NB_TOK - NB_MPREP) * 256 + t;
        int stride = NB_COPY * 256;
        for (int k = i; k < nM; k += stride) out_m4[k] = m4[k];
        for (int k = i; k < nS; k += stride) out_s4[k] = s_in4[k];
        for (int k = i; k < nMu; k += stride) out_mu4[k] = mu4[k];
        for (int k = i; k < nLu; k += stride) out_lu4[k] = lu4[k];
    }
}

// Cauchy-Schwarz screen via bf16 tensor cores
__global__ void k_screen() {
    __shared__ __align__(16) __nv_bfloat16 sPi[TB * LDPB];
    __shared__ __align__(16) __nv_bfloat16 sPj[TB * LDPB];
    __shared__ float sri[TB], srj[TB];
    int kblk = blockIdx.x;
    int bi = (int)((sqrtf(8.f * (float)kblk + 1.f) - 1.f) * 0.5f);
    while ((bi + 1) * (bi + 2) / 2 <= kblk) bi++;
    while (bi * (bi + 1) / 2 > kblk) bi--;
    int bj = kblk - bi * (bi + 1) / 2;
    int i0 = bi * TB, j0 = bj * TB;
    int t = threadIdx.x, lane = t & 31, wid = t >> 5;

    for (int it = t; it < TB * 8; it += 256) {
        int r = it >> 3, c = it & 7;
        *(uint4*)&sPi[r * LDPB + c * 8] = *(const uint4*)&g_Pb[(size_t)(i0 + r) * PD + c * 8];
        *(uint4*)&sPj[r * LDPB + c * 8] = *(const uint4*)&g_Pb[(size_t)(j0 + r) * PD + c * 8];
    }
    if (t < TB) { sri[t] = g_res[i0 + t]; srj[t] = g_res[j0 + t]; }
    __syncthreads();

    int warp_r = wid >> 2, warp_c = wid & 3;
    int rbase = warp_r * 64, cbase = warp_c * 32;
    uint32_t smem_i = (uint32_t)__cvta_generic_to_shared(sPi);
    uint32_t smem_j = (uint32_t)__cvta_generic_to_shared(sPj);

    float acc[4][4][4];
#pragma unroll
    for (int mt = 0; mt < 4; mt++)
#pragma unroll
        for (int nt = 0; nt < 4; nt++)
#pragma unroll
            for (int r = 0; r < 4; r++) acc[mt][nt][r] = 0.f;

#pragma unroll
    for (int ks = 0; ks < 4; ks++) {
        uint32_t afr[4][4];
        uint32_t bfr[4][2];
#pragma unroll
        for (int mt = 0; mt < 4; mt++) {
            int row = rbase + mt * 16 + (lane & 15);
            int col = ks * 16 + ((lane >> 4) << 3);
            ldsm4(smem_i + (uint32_t)(row * LDPB + col) * 2u,
                  afr[mt][0], afr[mt][1], afr[mt][2], afr[mt][3]);
        }
#pragma unroll
        for (int nt = 0; nt < 4; nt++) {
            int row = cbase + nt * 8 + (lane & 7);
            int col = ks * 16 + (lane & 8);
            ldsm2(smem_j + (uint32_t)(row * LDPB + col) * 2u,
                  bfr[nt][0], bfr[nt][1]);
        }
#pragma unroll
        for (int mt = 0; mt < 4; mt++)
#pragma unroll
            for (int nt = 0; nt < 4; nt++)
                mma16816(acc[mt][nt][0], acc[mt][nt][1], acc[mt][nt][2], acc[mt][nt][3],
                         afr[mt][0], afr[mt][1], afr[mt][2], afr[mt][3],
                         bfr[nt][0], bfr[nt][1]);
    }

    int gr = lane >> 2, tig = lane & 3;
#pragma unroll
    for (int mt = 0; mt < 4; mt++) {
        int r0l = rbase + mt * 16 + gr;
#pragma unroll
        for (int nt = 0; nt < 4; nt++) {
            int c0l = cbase + nt * 8 + 2 * tig;
#pragma unroll
            for (int e = 0; e < 4; e++) {
                int rl = r0l + ((e >> 1) ? 8 : 0);
                int cl = c0l + (e & 1);
                int i = i0 + rl, j = j0 + cl;
                if (i > j) {
                    float bound = acc[mt][nt][e] + sri[rl] * srj[cl];
                    if (bound > SCREEN_T) {
                        int p = atomicAdd(&g_npairs, 1);
                        if (p < PAIR_CAP) { g_pairs[2 * p] = i; g_pairs[2 * p + 1] = j; }
                    }
                }
            }
        }
    }
}

__global__ void k_exactW(const float* __restrict__ m) {
    int t = threadIdx.x, lane = t & 31;
    int np = g_npairs;
    if (np <= PAIR_CAP) {
        int gw = (blockIdx.x * blockDim.x + t) >> 5;
        int nw = (gridDim.x * blockDim.x) >> 5;
        for (int p = gw; p < np; p += nw) {
            int i = g_pairs[2 * p], j = g_pairs[2 * p + 1];
            const float4* a = (const float4*)(m + (size_t)i * DIM);
            const float4* b = (const float4*)(m + (size_t)j * DIM);
            float s = 0.f;
#pragma unroll
            for (int k = 0; k < 8; k++) s += dot4(a[lane + 32 * k], b[lane + 32 * k]);
            s = wsum(s);
            if (!lane) {
                float cosv = s * rsqrtf(g_mn2[i] * g_mn2[j]);
                unsigned long long key =
                    ((unsigned long long)ordf(cosv) << 32) | (0xFFFFFFFFu - (unsigned)(i * MSZ + j));
                atomicMax(&g_intmax, key);
            }
        }
    } else {
        __shared__ unsigned long long bk_;
        if (t == 0) bk_ = 0ull;
        __syncthreads();
        for (int i = blockIdx.x; i < MSZ; i += gridDim.x) {
            if (i == 0) continue;
            float bc = -2.f; int bf = 0;
            for (int j = t; j < i; j += 256) {
                float s = 0.f;
                const float* mi = m + (size_t)i * DIM;
                const float* mj = m + (size_t)j * DIM;
                for (int e = 0; e < DIM; e++) s += mi[e] * mj[e];
                float c = s * rsqrtf(g_mn2[i] * g_mn2[j]);
                if (c > bc) { bc = c; bf = i * MSZ + j; }
            }
            unsigned long long key = ((unsigned long long)ordf(bc) << 32) | (0xFFFFFFFFu - (unsigned)bf);
            atomicMax(&bk_, key);
        }
        __syncthreads();
        if (t == 0) atomicMax(&g_intmax, bk_);
    }
}

// parallel partial reduction: 64 blocks (16 k-groups x 4 col-groups), atomicAdd into g_mean
__global__ void k_lred() {
    int b = blockIdx.x, t = threadIdx.x;
    int kg = b >> 2, cg = b & 3;
    int c = cg * 256 + t;
    float s = 0.f;
#pragma unroll
    for (int k = kg * 8; k < kg * 8 + 8; k++) s += g_lpart[k * DIM + c];
    atomicAdd(&g_mean[c], s / (float)LSZ);
}

// q = wq @ mean + bq, 1 row/warp across 128 CTAs
__global__ void k_q(const float* __restrict__ wq, const float* __restrict__ bq) {
    int t = threadIdx.x, lane = t & 31, w = t >> 5;
    int j = blockIdx.x * 8 + w;
    const float4* mr = (const float4*)g_mean;
    const float4* wr = (const float4*)(wq + (size_t)j * DIM);
    float acc = 0.f;
#pragma unroll
    for (int k = 0; k < 8; k++) acc += dot4(wr[lane + 32 * k], mr[lane + 32 * k]);
    acc = wsum(acc);
    if (!lane) g_q[j] = acc + bq[j];
}

__global__ void k_v1(const float* __restrict__ wk) {
    int c  = blockIdx.x * 256 + threadIdx.x;
    int r0 = blockIdx.y * (DIM / NVCHUNK);
    float s = 0.f;
#pragma unroll
    for (int r = r0; r < r0 + (DIM / NVCHUNK); r++)
        s += g_q[r] * wk[(size_t)r * DIM + c];
    g_vpart[blockIdx.y * DIM + c] = s;
}

// single-block top-128: 3-pass byte radix select
__global__ void k_topk() {
    __shared__ int   hist[256];
    __shared__ float sval[COLLECT_CAP];
    __shared__ int   sidx[COLLECT_CAP];
    __shared__ int   s_cnt;
    __shared__ unsigned s_pref;
    __shared__ int   s_kneed;
    __shared__ float wv[32]; __shared__ int wi[32];
    int t = threadIdx.x;

    if (t == 0) { s_pref = 0; s_kneed = KPROM; }
    for (int pass = 0; pass < 3; pass++) {
        int shift = 24 - 8 * pass;
        if (t < 256) hist[t] = 0;
        __syncthreads();
        unsigned pref = s_pref;
        for (int i = t; i < CANDN; i += 1024) {
            unsigned key = ordf(g_norms[i]);
            if ((key >> (shift + 8)) == pref)
                atomicAdd(&hist[(key >> shift) & 255u], 1);
        }
        __syncthreads();
        if (t == 0) {
            int kneed = s_kneed, cum = 0, b = 255;
            for (; b >= 0; b--) {
                cum += hist[b];
                if (cum >= kneed) break;
            }
            if (b < 0) b = 0;
            s_kneed = kneed - (cum - hist[b]);
            s_pref = (s_pref << 8) | (unsigned)b;
        }
        __syncthreads();
    }
    unsigned P24 = s_pref;
    if (t == 0) s_cnt = 0;
    __syncthreads();
    for (int i = t; i < CANDN; i += 1024) {
        float v = g_norms[i];
        if ((ordf(v) >> 8) >= P24) {
            int p = atomicAdd(&s_cnt, 1);
            if (p < COLLECT_CAP) { sval[p] = v; sidx[p] = i; }
        }
    }
    __syncthreads();
    int M = s_cnt;
    if (M <= COLLECT_CAP) {
        for (int s = t; s < M; s += 1024) {
            float v = sval[s]; int id = sidx[s]; int r = 0;
            for (int f = 0; f < M; f++) {
                float vf = sval[f]; int idf = sidx[f];
                r += (vf > v) || (vf == v && idf < id);
            }
            if (r < KPROM) g_top[r] = id;
        }
    } else {
        for (int it = 0; it < KPROM; it++) {
            float bv = -3e38f; int bi = 0x7FFFFFFF;
            for (int i = t; i < CANDN; i += 1024) {
                float v = g_norms[i];
                if (v > bv || (v == bv && i < bi)) { bv = v; bi = i; }
            }
            bargmax(bv, bi, wv, wi);
            if (t == 0) { g_top[it] = bi; g_norms[bi] = -3e38f; }
            __syncthreads();
        }
    }
}

__global__ void k_scatter(const float* __restrict__ tok, const int* __restrict__ sptr,
                          float* __restrict__ out_s) {
    int j = blockIdx.x;
    int p = ((sptr[0] + j) % SSZ + SSZ) % SSZ;
    int src = g_top[j];
    ((float4*)(out_s + (size_t)p * DIM))[threadIdx.x] =
        ((const float4*)(tok + (size_t)src * DIM))[threadIdx.x];
}

__global__ void k_scores(const float* __restrict__ tok, const float* __restrict__ s_in,
                         const int* __restrict__ sptr) {
    __shared__ __align__(16) float sv[DIM];
    int t = threadIdx.x;                 // 1024
    {
        float s = 0.f;
#pragma unroll 8
        for (int k = 0; k < NVCHUNK; k++) s += g_vpart[k * DIM + t];
        sv[t] = s;
    }
    __syncthreads();
    int lane = t & 31, w = t >> 5;
    int sp = sptr[0];
    const float4* vr = (const float4*)sv;
    int i = blockIdx.x * 32 + w;
    const float4* sr = (const float4*)srow(i, sp, tok, s_in);
    float s = 0.f;
#pragma unroll
    for (int k = 0; k < 8; k++) s += dot4(sr[lane + 32 * k], vr[lane + 32 * k]);
    s = wsum(s);
    if (!lane) g_scores[i] = s;
}

__global__ void k_msims(const float* __restrict__ m, const float* __restrict__ tok,
                        const float* __restrict__ s_in, const int* __restrict__ sptr) {
    __shared__ __align__(16) float sc[DIM];
    __shared__ float sv_[32]; __shared__ int si_[32]; __shared__ float sb[32];
    int t = threadIdx.x;                 // 256
    float bv = -3e38f; int bi = 0x7FFFFFFF;
    for (int i = t; i < SSZ; i += 256) {
        float v = g_scores[i];
        if (v > bv || (v == bv && i < bi)) { bv = v; bi = i; }
    }
    bargmax(bv, bi, sv_, si_);
    int best = bi;
    int sp = sptr[0];
    const float* src = srow(best, sp, tok, s_in);
    for (int c = t; c < DIM; c += 256) sc[c] = src[c];
    __syncthreads();
    float n2p = 0.f;
    for (int c = t; c < DIM; c += 256) n2p += sc[c] * sc[c];
    float n2 = bsum(n2p, sb);
    if (blockIdx.x == 0) {
        for (int c = t; c < DIM; c += 256) g_cand[c] = sc[c];
        if (t == 0) g_candn2 = n2;
    }
    float rc = rsqrtf(n2);
    int lane = t & 31;
    const float4* cr = (const float4*)sc;
    for (int w = (blockIdx.x * 256 + t) >> 5; w < MSZ; w += (gridDim.x * 256) >> 5) {
        const float4* mr = (const float4*)(m + (size_t)w * DIM);
        float dc = 0.f;
#pragma unroll
        for (int k = 0; k < 8; k++) dc += dot4(mr[lane + 32 * k], cr[lane + 32 * k]);
        dc = wsum(dc);
        if (!lane) g_sims[w] = dc * rsqrtf(g_mn2[w]) * rc;
    }
}

__global__ void k_decideltier(const float* __restrict__ m, const float* __restrict__ mu,
                              const float* __restrict__ l_in, const float* __restrict__ lu,
                              const int* __restrict__ sptr,
                              float* __restrict__ out_m, float* __restrict__ out_mu,
                              float* __restrict__ out_l, float* __restrict__ out_lu,
                              float* __restrict__ out_ptr) {
    __shared__ float sv[32]; __shared__ int si[32]; __shared__ float sb[32];
    __shared__ int s_any;
    int t = threadIdx.x;                 // 1024
    if (t == 0) s_any = 0;
    __syncthreads();
    float musum = 0.f, mn = 3e38f; int mni = 0x7FFFFFFF; int anyz = 0;
    for (int i = t; i < MSZ; i += 1024) {
        float u = mu[i];
        musum += u;
        if (u < mn) { mn = u; mni = i; }
        anyz |= (u == 0.f);
    }
    if (anyz) atomicOr(&s_any, 1);
    float mu_mean = bsum(musum, sb) / (float)MSZ;
    bargmin(mn, mni, sv, si);
    int li = mni;
    __syncthreads();
    int any0 = s_any;
    float smax = -3e38f; int smi = 0x7FFFFFFF;
    for (int i = t; i < MSZ; i += 1024) {
        float s = g_sims[i];
        if (s > smax || (s == smax && i < smi)) { smax = s; smi = i; }
    }
    bargmax(smax, smi, sv, si);
    int msi = smi; float simcand = smax;
    float cosint = -2.f; int i1 = 0, i2 = 0;
    if (g_npairs > 0) {
        unsigned long long kk = g_intmax;
        cosint = deordf((unsigned)(kk >> 32));
        unsigned fl = 0xFFFFFFFFu - (unsigned)(kk & 0xFFFFFFFFu);
        i1 = fl / MSZ; i2 = fl % MSZ;
    }
    if (any0) {
        out_m[(size_t)li * DIM + t] = g_cand[t];
        if (t == 0) out_mu[li] = mu_mean + 1e-5f;
    } else if (simcand > MERGE_T) {
        float merged = (m[(size_t)msi * DIM + t] + g_cand[t]) * 0.5f;
        float n2 = bsum(merged * merged, sb);
        float dn = fmaxf(sqrtf(n2), 1e-12f);
        out_m[(size_t)msi * DIM + t] = merged / dn;
        if (t == 0) out_mu[msi] = (mu[msi] + mu_mean) * 0.5f;
    } else if (cosint > MERGE_T) {
        float merged = (m[(size_t)i1 * DIM + t] + m[(size_t)i2 * DIM + t]) * 0.5f;
        float n2 = bsum(merged * merged, sb);
        float dn = fmaxf(sqrtf(n2), 1e-12f);
        out_m[(size_t)i1 * DIM + t] = merged / dn;
        out_m[(size_t)i2 * DIM + t] = g_cand[t];
        if (t == 0) {
            float nu1 = (mu[i1] + mu[i2]) * 0.5f;
            out_mu[i1] = nu1;
            float mean2 = mu_mean + (nu1 - mu[i1]) / (float)MSZ;
            out_mu[i2] = mean2 + 1e-5f;
        }
    } else {
        if (g_candn2 > g_mn2[li]) {
            out_m[(size_t)li * DIM + t] = g_cand[t];
            if (t == 0) out_mu[li] = mu_mean + 1e-5f;
        }
    }
    __syncthreads();

    float mx = -3e38f; int mxi = 0x7FFFFFFF;
    for (int i = t; i < MSZ; i += 1024) {
        float u = out_mu[i];
        if (u > mx || (u == mx && i < mxi)) { mx = u; mxi = i; }
    }
    bargmax(mx, mxi, sv, si);
    int mi = mxi;
    float lsum = 0.f, lmn = 3e38f; int lmni = 0x7FFFFFFF;
    for (int i = t; i < LSZ; i += 1024) {
        float u = lu[i];
        lsum += u;
        if (u < lmn) { lmn = u; lmni = i; }
    }
    float ltot = bsum(lsum, sb);
    bargmin(lmn, lmni, sv, si);
    int lj = lmni;
    out_l[(size_t)lj * DIM + t] =
        0.9f * l_in[(size_t)lj * DIM + t] + 0.1f * out_m[(size_t)mi * DIM + t];
    if (t == 0) {
        out_lu[lj] = ltot / (float)LSZ;
        out_ptr[0] = (float)(((sptr[0] + KPROM) % SSZ + SSZ) % SSZ);
    }
}

// ------------- host -------------
extern "C" void kernel_launch(void* const* d_in, const int* in_sizes, int n_in,
                              void* d_out, int out_size) {
    const float* tok  = (const float*)d_in[0];
    const float* s_in = (const float*)d_in[1];
    const float* m_in = (const float*)d_in[2];
    const float* l_in = (const float*)d_in[3];
    const float* mu   = (const float*)d_in[4];
    const float* lu   = (const float*)d_in[5];
    const float* wq   = (const float*)d_in[6];
    const float* bq   = (const float*)d_in[7];
    const float* wk   = (const float*)d_in[8];
    const int*   sptr = (const int*)d_in[10];

    float* out    = (float*)d_out;
    float* out_s  = out;
    float* out_m  = out_s + (size_t)SSZ * DIM;
    float* out_l  = out_m + (size_t)MSZ * DIM;
    float* out_mu = out_l + (size_t)LSZ * DIM;
    float* out_lu = out_mu + MSZ;
    float* out_ptr = out_lu + LSZ;

    static cudaStream_t sA = 0, sB = 0, sC = 0;
    static cudaEvent_t evStream = 0, evTopk = 0, evA = 0, evB = 0, evC = 0;
    if (!sA) {
        cudaStreamCreateWithFlags(&sA, cudaStreamNonBlocking);
        cudaStreamCreateWithFlags(&sB, cudaStreamNonBlocking);
        cudaStreamCreateWithFlags(&sC, cudaStreamNonBlocking);
        cudaEventCreateWithFlags(&evStream, cudaEventDisableTiming);
        cudaEventCreateWithFlags(&evTopk, cudaEventDisableTiming);
        cudaEventCreateWithFlags(&evA, cudaEventDisableTiming);
        cudaEventCreateWithFlags(&evB, cudaEventDisableTiming);
        cudaEventCreateWithFlags(&evC, cudaEventDisableTiming);
    }

    // 1) streaming megakernel (stream 0), then fork
    k_stream<<<NB_TOTAL, 256>>>(tok, m_in, l_in, out_l,
                                (const float4*)s_in, (float4*)out_s,
                                (const float4*)m_in, (float4*)out_m,
                                (const float4*)mu, (float4*)out_mu,
                                (const float4*)lu, (float4*)out_lu);
    cudaEventRecord(evStream, 0);

    // stream 0: screen -> exactW
    k_screen<<<NTRI, 256>>>();
    k_exactW<<<64, 256>>>(m_in);

    // branch B: lred (parallel+atomic) -> q -> v1
    cudaStreamWaitEvent(sB, evStream, 0);
    k_lred<<<64, 256, 0, sB>>>();
    k_q<<<128, 256, 0, sB>>>(wq, bq);
    k_v1<<<dim3(DIM / 256, NVCHUNK), 256, 0, sB>>>(wk);
    cudaEventRecord(evB, sB);

    // branch C: topk -> (wait evB) scores -> msims
    cudaStreamWaitEvent(sC, evStream, 0);
    k_topk<<<1, 1024, 0, sC>>>();
    cudaEventRecord(evTopk, sC);
    cudaStreamWaitEvent(sC, evB, 0);
    k_scores<<<16, 1024, 0, sC>>>(tok, s_in, sptr);
    k_msims<<<256, 256, 0, sC>>>(m_in, tok, s_in, sptr);
    cudaEventRecord(evC, sC);

    // branch A: scatter
    cudaStreamWaitEvent(sA, evTopk, 0);
    k_scatter<<<KPROM, 256, 0, sA>>>(tok, sptr, out_s);
    cudaEventRecord(evA, sA);

    // join + tail
    cudaStreamWaitEvent(0, evC, 0);
    cudaStreamWaitEvent(0, evA, 0);
    k_decideltier<<<1, 1024>>>(m_in, mu, l_in, lu, sptr,
                               out_m, out_mu, out_l, out_lu, out_ptr);
}

// round 16
// speedup vs baseline: 1.0493x; 1.0493x over previous
#include <cuda_runtime.h>
#include <cuda_bf16.h>
#include <cstdint>

#define DIM   1024
#define CANDN 16384
#define SSZ   512
#define MSZ   4096
#define LSZ   8192
#define KPROM 128
#define PD    64
#define PAIR_CAP 65536
#define NLCHUNK 512
#define NVCHUNK 64
#define TB   128
#define NBT  32
#define NTRI (NBT*(NBT+1)/2)
#define LDPB 72
#define COLLECT_CAP 2048
#define SCREEN_T 0.974f
#define MERGE_T  0.98f

// balanced block partition of k_stream (4736 = 32 waves x 148 SMs)
#define NB_LMEAN 2048
#define NB_TOK   2048
#define NB_MPREP 512
#define NB_COPY  128
#define NB_TOTAL (NB_LMEAN + NB_TOK + NB_MPREP + NB_COPY)

// ------------- scratch -------------
__device__ float g_norms[CANDN];
__device__ int   g_top[KPROM];
__device__ float g_lpart[NLCHUNK * DIM];
__device__ float g_mean[DIM];
__device__ float g_q[DIM];
__device__ float g_vpart[NVCHUNK * DIM];
__device__ float g_scores[SSZ];
__device__ float g_cand[DIM];
__device__ float g_candn2;
__device__ float g_mn2[MSZ];
__device__ float g_sims[MSZ];
__device__ __nv_bfloat16 g_Pb[MSZ * PD];
__device__ float g_res[MSZ];
__device__ int   g_pairs[PAIR_CAP * 2];
__device__ int   g_npairs;
__device__ unsigned long long g_intmax;

// ------------- helpers -------------
__device__ __forceinline__ float dot4(float4 a, float4 b) {
    return a.x*b.x + a.y*b.y + a.z*b.z + a.w*b.w;
}
__device__ __forceinline__ float wsum(float v) {
#pragma unroll
    for (int o = 16; o; o >>= 1) v += __shfl_xor_sync(0xFFFFFFFFu, v, o);
    return v;
}
__device__ __forceinline__ unsigned ordf(float f) {
    unsigned u = __float_as_uint(f);
    return (u & 0x80000000u) ? ~u : (u | 0x80000000u);
}
__device__ __forceinline__ float deordf(unsigned u) {
    return (u & 0x80000000u) ? __uint_as_float(u & 0x7FFFFFFFu) : __uint_as_float(~u);
}
__device__ __forceinline__ float bsum(float v, float* sbuf) {
    int t = threadIdx.x, lane = t & 31, wid = t >> 5;
    v = wsum(v);
    if (!lane) sbuf[wid] = v;
    __syncthreads();
    int nw = blockDim.x >> 5;
    if (wid == 0) {
        float x = (lane < nw) ? sbuf[lane] : 0.f;
        x = wsum(x);
        if (!lane) sbuf[0] = x;
    }
    __syncthreads();
    v = sbuf[0];
    __syncthreads();
    return v;
}
__device__ __forceinline__ void bargmax(float& bv, int& bi, float* sv, int* si) {
    int t = threadIdx.x, lane = t & 31, wid = t >> 5;
#pragma unroll
    for (int o = 16; o; o >>= 1) {
        float ov = __shfl_xor_sync(0xFFFFFFFFu, bv, o);
        int   oi = __shfl_xor_sync(0xFFFFFFFFu, bi, o);
        if (ov > bv || (ov == bv && oi < bi)) { bv = ov; bi = oi; }
    }
    if (!lane) { sv[wid] = bv; si[wid] = bi; }
    __syncthreads();
    int nw = blockDim.x >> 5;
    if (wid == 0) {
        float xv = (lane < nw) ? sv[lane] : -3e38f;
        int   xi = (lane < nw) ? si[lane] : 0x7FFFFFFF;
#pragma unroll
        for (int o = 16; o; o >>= 1) {
            float ov = __shfl_xor_sync(0xFFFFFFFFu, xv, o);
            int   oi = __shfl_xor_sync(0xFFFFFFFFu, xi, o);
            if (ov > xv || (ov == xv && oi < xi)) { xv = ov; xi = oi; }
        }
        if (!lane) { sv[0] = xv; si[0] = xi; }
    }
    __syncthreads();
    bv = sv[0]; bi = si[0];
    __syncthreads();
}
__device__ __forceinline__ void bargmin(float& bv, int& bi, float* sv, int* si) {
    int t = threadIdx.x, lane = t & 31, wid = t >> 5;
#pragma unroll
    for (int o = 16; o; o >>= 1) {
        float ov = __shfl_xor_sync(0xFFFFFFFFu, bv, o);
        int   oi = __shfl_xor_sync(0xFFFFFFFFu, bi, o);
        if (ov < bv || (ov == bv && oi < bi)) { bv = ov; bi = oi; }
    }
    if (!lane) { sv[wid] = bv; si[wid] = bi; }
    __syncthreads();
    int nw = blockDim.x >> 5;
    if (wid == 0) {
        float xv = (lane < nw) ? sv[lane] : 3e38f;
        int   xi = (lane < nw) ? si[lane] : 0x7FFFFFFF;
#pragma unroll
        for (int o = 16; o; o >>= 1) {
            float ov = __shfl_xor_sync(0xFFFFFFFFu, xv, o);
            int   oi = __shfl_xor_sync(0xFFFFFFFFu, xi, o);
            if (ov < xv || (ov == xv && oi < xi)) { xv = ov; xi = oi; }
        }
        if (!lane) { sv[0] = xv; si[0] = xi; }
    }
    __syncthreads();
    bv = sv[0]; bi = si[0];
    __syncthreads();
}

__device__ __forceinline__ void ldsm4(uint32_t addr, uint32_t& r0, uint32_t& r1,
                                      uint32_t& r2, uint32_t& r3) {
    asm volatile("ldmatrix.sync.aligned.m8n8.x4.shared.b16 {%0,%1,%2,%3}, [%4];"
                 : "=r"(r0), "=r"(r1), "=r"(r2), "=r"(r3) : "r"(addr));
}
__device__ __forceinline__ void ldsm2(uint32_t addr, uint32_t& r0, uint32_t& r1) {
    asm volatile("ldmatrix.sync.aligned.m8n8.x2.shared.b16 {%0,%1}, [%2];"
                 : "=r"(r0), "=r"(r1) : "r"(addr));
}
__device__ __forceinline__ void mma16816(float& c0, float& c1, float& c2, float& c3,
                                         uint32_t a0, uint32_t a1, uint32_t a2, uint32_t a3,
                                         uint32_t b0, uint32_t b1) {
    asm volatile("mma.sync.aligned.m16n8k16.row.col.f32.bf16.bf16.f32 "
                 "{%0,%1,%2,%3}, {%4,%5,%6,%7}, {%8,%9}, {%0,%1,%2,%3};"
                 : "+f"(c0), "+f"(c1), "+f"(c2), "+f"(c3)
                 : "r"(a0), "r"(a1), "r"(a2), "r"(a3), "r"(b0), "r"(b1));
}

__device__ __forceinline__ const float* srow(int i, int sp,
                                             const float* __restrict__ tok,
                                             const float* __restrict__ s_in) {
    int d = ((i - sp) % SSZ + SSZ) % SSZ;
    if (d < KPROM) return tok + (size_t)g_top[d] * DIM;
    return s_in + (size_t)i * DIM;
}

// ------------- kernels -------------

// streaming megakernel (balanced): lmean | toknorm | mprep(+m copy) | s/mu/lu copies
__global__ void __launch_bounds__(256) k_stream(
    const float* __restrict__ tok, const float* __restrict__ m,
    const float* __restrict__ l_in, float* __restrict__ out_l,
    const float4* __restrict__ s_in4, float4* __restrict__ out_s4,
    float4* __restrict__ out_m4,
    const float4* __restrict__ mu4, float4* __restrict__ out_mu4,
    const float4* __restrict__ lu4, float4* __restrict__ out_lu4)
{
    int b = blockIdx.x, t = threadIdx.x;
    if (b == 0 && t == 0) { g_npairs = 0; g_intmax = 0ull; }

    if (b < NB_LMEAN) {
        // l copy + partial sums: 4 col-groups x 512 row-chunks of 16 rows
        int c  = (b & 3) * 256 + t;
        int rc = b >> 2;
        int r0 = rc * (LSZ / NLCHUNK);   // 16 rows
        float s = 0.f;
#pragma unroll
        for (int r = r0; r < r0 + (LSZ / NLCHUNK); r++) {
            float v = l_in[(size_t)r * DIM + c];
            out_l[(size_t)r * DIM + c] = v;
            s += v;
        }
        g_lpart[(size_t)rc * DIM + c] = s;
    } else if (b < NB_LMEAN + NB_TOK) {
        int w = ((b - NB_LMEAN) * 256 + t) >> 5;
        int lane = t & 31;
        const float4* p = (const float4*)(tok + (size_t)w * DIM);
        float s = 0.f;
#pragma unroll
        for (int k = 0; k < 8; k++) { float4 v = p[lane + 32 * k]; s += dot4(v, v); }
        s = wsum(s);
        if (!lane) g_norms[w] = s;
    } else if (b < NB_LMEAN + NB_TOK + NB_MPREP) {
        // m row norms + bf16 prefix + residual + WRITE out_m (single read of m)
        int w = ((b - NB_LMEAN - NB_TOK) * 256 + t) >> 5;
        int lane = t & 31;
        const float4* mr = (const float4*)(m + (size_t)w * DIM);
        float4* mo = (float4*)((float*)out_m4 + (size_t)w * DIM);
        float n2 = 0.f;
        float4 vv[8];
#pragma unroll
        for (int k = 0; k < 8; k++) {
            vv[k] = mr[lane + 32 * k];
            n2 += dot4(vv[k], vv[k]);
        }
#pragma unroll
        for (int k = 0; k < 8; k++) mo[lane + 32 * k] = vv[k];
        n2 = wsum(n2);
        float sp2 = (lane < 16) ? dot4(vv[0], vv[0]) : 0.f;
        sp2 = wsum(sp2);
        float rinv = rsqrtf(n2);
        if (lane < 16) {
            __nv_bfloat162 lo = __floats2bfloat162_rn(vv[0].x * rinv, vv[0].y * rinv);
            __nv_bfloat162 hi = __floats2bfloat162_rn(vv[0].z * rinv, vv[0].w * rinv);
            __nv_bfloat162* dst = (__nv_bfloat162*)(g_Pb + (size_t)w * PD + lane * 4);
            dst[0] = lo;
            dst[1] = hi;
        }
        if (!lane) {
            g_mn2[w] = n2;
            g_res[w] = sqrtf(fmaxf(0.f, 1.f - sp2 * rinv * rinv));
        }
    } else {
        // grid-stride copies of out_s, out_mu, out_lu; first 4 blocks zero g_mean
        int cb = b - NB_LMEAN - NB_TOK - NB_MPREP;
        if (cb < 4) g_mean[cb * 256 + t] = 0.f;
        const int nS = SSZ * DIM / 4, nMu = MSZ / 4, nLu = LSZ / 4;
        int i = cb * 256 + t;
        int stride = NB_COPY * 256;
        for (int k = i; k < nS; k += stride) out_s4[k] = s_in4[k];
        for (int k = i; k < nMu; k += stride) out_mu4[k] = mu4[k];
        for (int k = i; k < nLu; k += stride) out_lu4[k] = lu4[k];
    }
}

// Cauchy-Schwarz screen via bf16 tensor cores
__global__ void k_screen() {
    __shared__ __align__(16) __nv_bfloat16 sPi[TB * LDPB];
    __shared__ __align__(16) __nv_bfloat16 sPj[TB * LDPB];
    __shared__ float sri[TB], srj[TB];
    int kblk = blockIdx.x;
    int bi = (int)((sqrtf(8.f * (float)kblk + 1.f) - 1.f) * 0.5f);
    while ((bi + 1) * (bi + 2) / 2 <= kblk) bi++;
    while (bi * (bi + 1) / 2 > kblk) bi--;
    int bj = kblk - bi * (bi + 1) / 2;
    int i0 = bi * TB, j0 = bj * TB;
    int t = threadIdx.x, lane = t & 31, wid = t >> 5;

    for (int it = t; it < TB * 8; it += 256) {
        int r = it >> 3, c = it & 7;
        *(uint4*)&sPi[r * LDPB + c * 8] = *(const uint4*)&g_Pb[(size_t)(i0 + r) * PD + c * 8];
        *(uint4*)&sPj[r * LDPB + c * 8] = *(const uint4*)&g_Pb[(size_t)(j0 + r) * PD + c * 8];
    }
    if (t < TB) { sri[t] = g_res[i0 + t]; srj[t] = g_res[j0 + t]; }
    __syncthreads();

    int warp_r = wid >> 2, warp_c = wid & 3;
    int rbase = warp_r * 64, cbase = warp_c * 32;
    uint32_t smem_i = (uint32_t)__cvta_generic_to_shared(sPi);
    uint32_t smem_j = (uint32_t)__cvta_generic_to_shared(sPj);

    float acc[4][4][4];
#pragma unroll
    for (int mt = 0; mt < 4; mt++)
#pragma unroll
        for (int nt = 0; nt < 4; nt++)
#pragma unroll
            for (int r = 0; r < 4; r++) acc[mt][nt][r] = 0.f;

#pragma unroll
    for (int ks = 0; ks < 4; ks++) {
        uint32_t afr[4][4];
        uint32_t bfr[4][2];
#pragma unroll
        for (int mt = 0; mt < 4; mt++) {
            int row = rbase + mt * 16 + (lane & 15);
            int col = ks * 16 + ((lane >> 4) << 3);
            ldsm4(smem_i + (uint32_t)(row * LDPB + col) * 2u,
                  afr[mt][0], afr[mt][1], afr[mt][2], afr[mt][3]);
        }
#pragma unroll
        for (int nt = 0; nt < 4; nt++) {
            int row = cbase + nt * 8 + (lane & 7);
            int col = ks * 16 + (lane & 8);
            ldsm2(smem_j + (uint32_t)(row * LDPB + col) * 2u,
                  bfr[nt][0], bfr[nt][1]);
        }
#pragma unroll
        for (int mt = 0; mt < 4; mt++)
#pragma unroll
            for (int nt = 0; nt < 4; nt++)
                mma16816(acc[mt][nt][0], acc[mt][nt][1], acc[mt][nt][2], acc[mt][nt][3],
                         afr[mt][0], afr[mt][1], afr[mt][2], afr[mt][3],
                         bfr[nt][0], bfr[nt][1]);
    }

    int gr = lane >> 2, tig = lane & 3;
#pragma unroll
    for (int mt = 0; mt < 4; mt++) {
        int r0l = rbase + mt * 16 + gr;
#pragma unroll
        for (int nt = 0; nt < 4; nt++) {
            int c0l = cbase + nt * 8 + 2 * tig;
#pragma unroll
            for (int e = 0; e < 4; e++) {
                int rl = r0l + ((e >> 1) ? 8 : 0);
                int cl = c0l + (e & 1);
                int i = i0 + rl, j = j0 + cl;
                if (i > j) {
                    float bound = acc[mt][nt][e] + sri[rl] * srj[cl];
                    if (bound > SCREEN_T) {
                        int p = atomicAdd(&g_npairs, 1);
                        if (p < PAIR_CAP) { g_pairs[2 * p] = i; g_pairs[2 * p + 1] = j; }
                    }
                }
            }
        }
    }
}

__global__ void k_exactW(const float* __restrict__ m) {
    int t = threadIdx.x, lane = t & 31;
    int np = g_npairs;
    if (np <= PAIR_CAP) {
        int gw = (blockIdx.x * blockDim.x + t) >> 5;
        int nw = (gridDim.x * blockDim.x) >> 5;
        for (int p = gw; p < np; p += nw) {
            int i = g_pairs[2 * p], j = g_pairs[2 * p + 1];
            const float4* a = (const float4*)(m + (size_t)i * DIM);
            const float4* b = (const float4*)(m + (size_t)j * DIM);
            float s = 0.f;
#pragma unroll
            for (int k = 0; k < 8; k++) s += dot4(a[lane + 32 * k], b[lane + 32 * k]);
            s = wsum(s);
            if (!lane) {
                float cosv = s * rsqrtf(g_mn2[i] * g_mn2[j]);
                unsigned long long key =
                    ((unsigned long long)ordf(cosv) << 32) | (0xFFFFFFFFu - (unsigned)(i * MSZ + j));
                atomicMax(&g_intmax, key);
            }
        }
    } else {
        __shared__ unsigned long long bk_;
        if (t == 0) bk_ = 0ull;
        __syncthreads();
        for (int i = blockIdx.x; i < MSZ; i += gridDim.x) {
            if (i == 0) continue;
            float bc = -2.f; int bf = 0;
            for (int j = t; j < i; j += 256) {
                float s = 0.f;
                const float* mi = m + (size_t)i * DIM;
                const float* mj = m + (size_t)j * DIM;
                for (int e = 0; e < DIM; e++) s += mi[e] * mj[e];
                float c = s * rsqrtf(g_mn2[i] * g_mn2[j]);
                if (c > bc) { bc = c; bf = i * MSZ + j; }
            }
            unsigned long long key = ((unsigned long long)ordf(bc) << 32) | (0xFFFFFFFFu - (unsigned)bf);
            atomicMax(&bk_, key);
        }
        __syncthreads();
        if (t == 0) atomicMax(&g_intmax, bk_);
    }
}

// parallel partial reduction over 512 partials: 256 blocks (64 kg x 4 cg), atomicAdd
__global__ void k_lred() {
    int b = blockIdx.x, t = threadIdx.x;
    int kg = b >> 2, cg = b & 3;
    int c = cg * 256 + t;
    float s = 0.f;
#pragma unroll
    for (int k = kg * 8; k < kg * 8 + 8; k++) s += g_lpart[(size_t)k * DIM + c];
    atomicAdd(&g_mean[c], s / (float)LSZ);
}

// q = wq @ mean + bq, 1 row/warp across 128 CTAs
__global__ void k_q(const float* __restrict__ wq, const float* __restrict__ bq) {
    int t = threadIdx.x, lane = t & 31, w = t >> 5;
    int j = blockIdx.x * 8 + w;
    const float4* mr = (const float4*)g_mean;
    const float4* wr = (const float4*)(wq + (size_t)j * DIM);
    float acc = 0.f;
#pragma unroll
    for (int k = 0; k < 8; k++) acc += dot4(wr[lane + 32 * k], mr[lane + 32 * k]);
    acc = wsum(acc);
    if (!lane) g_q[j] = acc + bq[j];
}

__global__ void k_v1(const float* __restrict__ wk) {
    int c  = blockIdx.x * 256 + threadIdx.x;
    int r0 = blockIdx.y * (DIM / NVCHUNK);
    float s = 0.f;
#pragma unroll
    for (int r = r0; r < r0 + (DIM / NVCHUNK); r++)
        s += g_q[r] * wk[(size_t)r * DIM + c];
    g_vpart[blockIdx.y * DIM + c] = s;
}

// single-block top-128: 3-pass byte radix select
__global__ void k_topk() {
    __shared__ int   hist[256];
    __shared__ float sval[COLLECT_CAP];
    __shared__ int   sidx[COLLECT_CAP];
    __shared__ int   s_cnt;
    __shared__ unsigned s_pref;
    __shared__ int   s_kneed;
    __shared__ float wv[32]; __shared__ int wi[32];
    int t = threadIdx.x;

    if (t == 0) { s_pref = 0; s_kneed = KPROM; }
    for (int pass = 0; pass < 3; pass++) {
        int shift = 24 - 8 * pass;
        if (t < 256) hist[t] = 0;
        __syncthreads();
        unsigned pref = s_pref;
        for (int i = t; i < CANDN; i += 1024) {
            unsigned key = ordf(g_norms[i]);
            if ((key >> (shift + 8)) == pref)
                atomicAdd(&hist[(key >> shift) & 255u], 1);
        }
        __syncthreads();
        if (t == 0) {
            int kneed = s_kneed, cum = 0, b = 255;
            for (; b >= 0; b--) {
                cum += hist[b];
                if (cum >= kneed) break;
            }
            if (b < 0) b = 0;
            s_kneed = kneed - (cum - hist[b]);
            s_pref = (s_pref << 8) | (unsigned)b;
        }
        __syncthreads();
    }
    unsigned P24 = s_pref;
    if (t == 0) s_cnt = 0;
    __syncthreads();
    for (int i = t; i < CANDN; i += 1024) {
        float v = g_norms[i];
        if ((ordf(v) >> 8) >= P24) {
            int p = atomicAdd(&s_cnt, 1);
            if (p < COLLECT_CAP) { sval[p] = v; sidx[p] = i; }
        }
    }
    __syncthreads();
    int M = s_cnt;
    if (M <= COLLECT_CAP) {
        for (int s = t; s < M; s += 1024) {
            float v = sval[s]; int id = sidx[s]; int r = 0;
            for (int f = 0; f < M; f++) {
                float vf = sval[f]; int idf = sidx[f];
                r += (vf > v) || (vf == v && idf < id);
            }
            if (r < KPROM) g_top[r] = id;
        }
    } else {
        for (int it = 0; it < KPROM; it++) {
            float bv = -3e38f; int bi = 0x7FFFFFFF;
            for (int i = t; i < CANDN; i += 1024) {
                float v = g_norms[i];
                if (v > bv || (v == bv && i < bi)) { bv = v; bi = i; }
            }
            bargmax(bv, bi, wv, wi);
            if (t == 0) { g_top[it] = bi; g_norms[bi] = -3e38f; }
            __syncthreads();
        }
    }
}

__global__ void k_scatter(const float* __restrict__ tok, const int* __restrict__ sptr,
                          float* __restrict__ out_s) {
    int j = blockIdx.x;
    int p = ((sptr[0] + j) % SSZ + SSZ) % SSZ;
    int src = g_top[j];
    ((float4*)(out_s + (size_t)p * DIM))[threadIdx.x] =
        ((const float4*)(tok + (size_t)src * DIM))[threadIdx.x];
}

__global__ void k_scores(const float* __restrict__ tok, const float* __restrict__ s_in,
                         const int* __restrict__ sptr) {
    __shared__ __align__(16) float sv[DIM];
    int t = threadIdx.x;                 // 1024
    {
        float s = 0.f;
#pragma unroll 8
        for (int k = 0; k < NVCHUNK; k++) s += g_vpart[k * DIM + t];
        sv[t] = s;
    }
    __syncthreads();
    int lane = t & 31, w = t >> 5;
    int sp = sptr[0];
    const float4* vr = (const float4*)sv;
    int i = blockIdx.x * 32 + w;
    const float4* sr = (const float4*)srow(i, sp, tok, s_in);
    float s = 0.f;
#pragma unroll
    for (int k = 0; k < 8; k++) s += dot4(sr[lane + 32 * k], vr[lane + 32 * k]);
    s = wsum(s);
    if (!lane) g_scores[i] = s;
}

__global__ void k_msims(const float* __restrict__ m, const float* __restrict__ tok,
                        const float* __restrict__ s_in, const int* __restrict__ sptr) {
    __shared__ __align__(16) float sc[DIM];
    __shared__ float sv_[32]; __shared__ int si_[32]; __shared__ float sb[32];
    int t = threadIdx.x;                 // 256
    float bv = -3e38f; int bi = 0x7FFFFFFF;
    for (int i = t; i < SSZ; i += 256) {
        float v = g_scores[i];
        if (v > bv || (v == bv && i < bi)) { bv = v; bi = i; }
    }
    bargmax(bv, bi, sv_, si_);
    int best = bi;
    int sp = sptr[0];
    const float* src = srow(best, sp, tok, s_in);
    for (int c = t; c < DIM; c += 256) sc[c] = src[c];
    __syncthreads();
    float n2p = 0.f;
    for (int c = t; c < DIM; c += 256) n2p += sc[c] * sc[c];
    float n2 = bsum(n2p, sb);
    if (blockIdx.x == 0) {
        for (int c = t; c < DIM; c += 256) g_cand[c] = sc[c];
        if (t == 0) g_candn2 = n2;
    }
    float rc = rsqrtf(n2);
    int lane = t & 31;
    const float4* cr = (const float4*)sc;
    for (int w = (blockIdx.x * 256 + t) >> 5; w < MSZ; w += (gridDim.x * 256) >> 5) {
        const float4* mr = (const float4*)(m + (size_t)w * DIM);
        float dc = 0.f;
#pragma unroll
        for (int k = 0; k < 8; k++) dc += dot4(mr[lane + 32 * k], cr[lane + 32 * k]);
        dc = wsum(dc);
        if (!lane) g_sims[w] = dc * rsqrtf(g_mn2[w]) * rc;
    }
}

__global__ void k_decideltier(const float* __restrict__ m, const float* __restrict__ mu,
                              const float* __restrict__ l_in, const float* __restrict__ lu,
                              const int* __restrict__ sptr,
                              float* __restrict__ out_m, float* __restrict__ out_mu,
                              float* __restrict__ out_l, float* __restrict__ out_lu,
                              float* __restrict__ out_ptr) {
    __shared__ float sv[32]; __shared__ int si[32]; __shared__ float sb[32];
    __shared__ int s_any;
    int t = threadIdx.x;                 // 1024
    if (t == 0) s_any = 0;
    __syncthreads();
    float musum = 0.f, mn = 3e38f; int mni = 0x7FFFFFFF; int anyz = 0;
    for (int i = t; i < MSZ; i += 1024) {
        float u = mu[i];
        musum += u;
        if (u < mn) { mn = u; mni = i; }
        anyz |= (u == 0.f);
    }
    if (anyz) atomicOr(&s_any, 1);
    float mu_mean = bsum(musum, sb) / (float)MSZ;
    bargmin(mn, mni, sv, si);
    int li = mni;
    __syncthreads();
    int any0 = s_any;
    float smax = -3e38f; int smi = 0x7FFFFFFF;
    for (int i = t; i < MSZ; i += 1024) {
        float s = g_sims[i];
        if (s > smax || (s == smax && i < smi)) { smax = s; smi = i; }
    }
    bargmax(smax, smi, sv, si);
    int msi = smi; float simcand = smax;
    float cosint = -2.f; int i1 = 0, i2 = 0;
    if (g_npairs > 0) {
        unsigned long long kk = g_intmax;
        cosint = deordf((unsigned)(kk >> 32));
        unsigned fl = 0xFFFFFFFFu - (unsigned)(kk & 0xFFFFFFFFu);
        i1 = fl / MSZ; i2 = fl % MSZ;
    }
    if (any0) {
        out_m[(size_t)li * DIM + t] = g_cand[t];
        if (t == 0) out_mu[li] = mu_mean + 1e-5f;
    } else if (simcand > MERGE_T) {
        float merged = (m[(size_t)msi * DIM + t] + g_cand[t]) * 0.5f;
        float n2 = bsum(merged * merged, sb);
        float dn = fmaxf(sqrtf(n2), 1e-12f);
        out_m[(size_t)msi * DIM + t] = merged / dn;
        if (t == 0) out_mu[msi] = (mu[msi] + mu_mean) * 0.5f;
    } else if (cosint > MERGE_T) {
        float merged = (m[(size_t)i1 * DIM + t] + m[(size_t)i2 * DIM + t]) * 0.5f;
        float n2 = bsum(merged * merged, sb);
        float dn = fmaxf(sqrtf(n2), 1e-12f);
        out_m[(size_t)i1 * DIM + t] = merged / dn;
        out_m[(size_t)i2 * DIM + t] = g_cand[t];
        if (t == 0) {
            float nu1 = (mu[i1] + mu[i2]) * 0.5f;
            out_mu[i1] = nu1;
            float mean2 = mu_mean + (nu1 - mu[i1]) / (float)MSZ;
            out_mu[i2] = mean2 + 1e-5f;
        }
    } else {
        if (g_candn2 > g_mn2[li]) {
            out_m[(size_t)li * DIM + t] = g_cand[t];
            if (t == 0) out_mu[li] = mu_mean + 1e-5f;
        }
    }
    __syncthreads();

    float mx = -3e38f; int mxi = 0x7FFFFFFF;
    for (int i = t; i < MSZ; i += 1024) {
        float u = out_mu[i];
        if (u > mx || (u == mx && i < mxi)) { mx = u; mxi = i; }
    }
    bargmax(mx, mxi, sv, si);
    int mi = mxi;
    float lsum = 0.f, lmn = 3e38f; int lmni = 0x7FFFFFFF;
    for (int i = t; i < LSZ; i += 1024) {
        float u = lu[i];
        lsum += u;
        if (u < lmn) { lmn = u; lmni = i; }
    }
    float ltot = bsum(lsum, sb);
    bargmin(lmn, lmni, sv, si);
    int lj = lmni;
    out_l[(size_t)lj * DIM + t] =
        0.9f * l_in[(size_t)lj * DIM + t] + 0.1f * out_m[(size_t)mi * DIM + t];
    if (t == 0) {
        out_lu[lj] = ltot / (float)LSZ;
        out_ptr[0] = (float)(((sptr[0] + KPROM) % SSZ + SSZ) % SSZ);
    }
}

// ------------- host -------------
extern "C" void kernel_launch(void* const* d_in, const int* in_sizes, int n_in,
                              void* d_out, int out_size) {
    const float* tok  = (const float*)d_in[0];
    const float* s_in = (const float*)d_in[1];
    const float* m_in = (const float*)d_in[2];
    const float* l_in = (const float*)d_in[3];
    const float* mu   = (const float*)d_in[4];
    const float* lu   = (const float*)d_in[5];
    const float* wq   = (const float*)d_in[6];
    const float* bq   = (const float*)d_in[7];
    const float* wk   = (const float*)d_in[8];
    const int*   sptr = (const int*)d_in[10];

    float* out    = (float*)d_out;
    float* out_s  = out;
    float* out_m  = out_s + (size_t)SSZ * DIM;
    float* out_l  = out_m + (size_t)MSZ * DIM;
    float* out_mu = out_l + (size_t)LSZ * DIM;
    float* out_lu = out_mu + MSZ;
    float* out_ptr = out_lu + LSZ;

    static cudaStream_t sA = 0, sB = 0, sC = 0;
    static cudaEvent_t evStream = 0, evTopk = 0, evA = 0, evB = 0, evC = 0;
    if (!sA) {
        cudaStreamCreateWithFlags(&sA, cudaStreamNonBlocking);
        cudaStreamCreateWithFlags(&sB, cudaStreamNonBlocking);
        cudaStreamCreateWithFlags(&sC, cudaStreamNonBlocking);
        cudaEventCreateWithFlags(&evStream, cudaEventDisableTiming);
        cudaEventCreateWithFlags(&evTopk, cudaEventDisableTiming);
        cudaEventCreateWithFlags(&evA, cudaEventDisableTiming);
        cudaEventCreateWithFlags(&evB, cudaEventDisableTiming);
        cudaEventCreateWithFlags(&evC, cudaEventDisableTiming);
    }

    // 1) balanced streaming megakernel (stream 0), then fork
    k_stream<<<NB_TOTAL, 256>>>(tok, m_in, l_in, out_l,
                                (const float4*)s_in, (float4*)out_s,
                                (float4*)out_m,
                                (const float4*)mu, (float4*)out_mu,
                                (const float4*)lu, (float4*)out_lu);
    cudaEventRecord(evStream, 0);

    // stream 0: screen -> exactW
    k_screen<<<NTRI, 256>>>();
    k_exactW<<<64, 256>>>(m_in);

    // branch B: lred -> q -> v1
    cudaStreamWaitEvent(sB, evStream, 0);
    k_lred<<<256, 256, 0, sB>>>();
    k_q<<<128, 256, 0, sB>>>(wq, bq);
    k_v1<<<dim3(DIM / 256, NVCHUNK), 256, 0, sB>>>(wk);
    cudaEventRecord(evB, sB);

    // branch C: topk -> (wait evB) scores -> msims
    cudaStreamWaitEvent(sC, evStream, 0);
    k_topk<<<1, 1024, 0, sC>>>();
    cudaEventRecord(evTopk, sC);
    cudaStreamWaitEvent(sC, evB, 0);
    k_scores<<<16, 1024, 0, sC>>>(tok, s_in, sptr);
    k_msims<<<256, 256, 0, sC>>>(m_in, tok, s_in, sptr);
    cudaEventRecord(evC, sC);

    // branch A: scatter
    cudaStreamWaitEvent(sA, evTopk, 0);
    k_scatter<<<KPROM, 256, 0, sA>>>(tok, sptr, out_s);
    cudaEventRecord(evA, sA);

    // join + tail
    cudaStreamWaitEvent(0, evC, 0);
    cudaStreamWaitEvent(0, evA, 0);
    k_decideltier<<<1, 1024>>>(m_in, mu, l_in, lu, sptr,
                               out_m, out_mu, out_l, out_lu, out_ptr);
}

// round 17
// speedup vs baseline: 1.0824x; 1.0315x over previous
#include <cuda_runtime.h>
#include <cuda_bf16.h>
#include <cstdint>

#define DIM   1024
#define CANDN 16384
#define SSZ   512
#define MSZ   4096
#define LSZ   8192
#define KPROM 128
#define PD    64
#define PAIR_CAP 65536
#define NLCHUNK 512
#define NVCHUNK 128
#define TB   128
#define NBT  32
#define NTRI (NBT*(NBT+1)/2)
#define LDPB 72
#define COLLECT_CAP 2048
#define SCREEN_T 0.974f
#define MERGE_T  0.98f

// streamA partition (lmean | toknorm), streamB partition (mprep | copies)
#define NB_LMEAN 2048
#define NB_TOK   2048
#define NB_A     (NB_LMEAN + NB_TOK)
#define NB_MPREP 512
#define NB_COPY  128
#define NB_B     (NB_MPREP + NB_COPY)

// ------------- scratch -------------
__device__ float g_norms[CANDN];
__device__ int   g_top[KPROM];
__device__ float g_lpart[NLCHUNK * DIM];
__device__ float g_mean[DIM];
__device__ float g_q[DIM];
__device__ float g_vpart[NVCHUNK * DIM];
__device__ float g_scores[SSZ];
__device__ float g_cand[DIM];
__device__ float g_candn2;
__device__ float g_mn2[MSZ];
__device__ float g_sims[MSZ];
__device__ __nv_bfloat16 g_Pb[MSZ * PD];
__device__ float g_res[MSZ];
__device__ int   g_pairs[PAIR_CAP * 2];
__device__ int   g_npairs;
__device__ unsigned long long g_intmax;

// ------------- helpers -------------
__device__ __forceinline__ float dot4(float4 a, float4 b) {
    return a.x*b.x + a.y*b.y + a.z*b.z + a.w*b.w;
}
__device__ __forceinline__ float wsum(float v) {
#pragma unroll
    for (int o = 16; o; o >>= 1) v += __shfl_xor_sync(0xFFFFFFFFu, v, o);
    return v;
}
__device__ __forceinline__ unsigned ordf(float f) {
    unsigned u = __float_as_uint(f);
    return (u & 0x80000000u) ? ~u : (u | 0x80000000u);
}
__device__ __forceinline__ float deordf(unsigned u) {
    return (u & 0x80000000u) ? __uint_as_float(u & 0x7FFFFFFFu) : __uint_as_float(~u);
}
__device__ __forceinline__ float bsum(float v, float* sbuf) {
    int t = threadIdx.x, lane = t & 31, wid = t >> 5;
    v = wsum(v);
    if (!lane) sbuf[wid] = v;
    __syncthreads();
    int nw = blockDim.x >> 5;
    if (wid == 0) {
        float x = (lane < nw) ? sbuf[lane] : 0.f;
        x = wsum(x);
        if (!lane) sbuf[0] = x;
    }
    __syncthreads();
    v = sbuf[0];
    __syncthreads();
    return v;
}
__device__ __forceinline__ void bargmax(float& bv, int& bi, float* sv, int* si) {
    int t = threadIdx.x, lane = t & 31, wid = t >> 5;
#pragma unroll
    for (int o = 16; o; o >>= 1) {
        float ov = __shfl_xor_sync(0xFFFFFFFFu, bv, o);
        int   oi = __shfl_xor_sync(0xFFFFFFFFu, bi, o);
        if (ov > bv || (ov == bv && oi < bi)) { bv = ov; bi = oi; }
    }
    if (!lane) { sv[wid] = bv; si[wid] = bi; }
    __syncthreads();
    int nw = blockDim.x >> 5;
    if (wid == 0) {
        float xv = (lane < nw) ? sv[lane] : -3e38f;
        int   xi = (lane < nw) ? si[lane] : 0x7FFFFFFF;
#pragma unroll
        for (int o = 16; o; o >>= 1) {
            float ov = __shfl_xor_sync(0xFFFFFFFFu, xv, o);
            int   oi = __shfl_xor_sync(0xFFFFFFFFu, xi, o);
            if (ov > xv || (ov == xv && oi < xi)) { xv = ov; xi = oi; }
        }
        if (!lane) { sv[0] = xv; si[0] = xi; }
    }
    __syncthreads();
    bv = sv[0]; bi = si[0];
    __syncthreads();
}
__device__ __forceinline__ void bargmin(float& bv, int& bi, float* sv, int* si) {
    int t = threadIdx.x, lane = t & 31, wid = t >> 5;
#pragma unroll
    for (int o = 16; o; o >>= 1) {
        float ov = __shfl_xor_sync(0xFFFFFFFFu, bv, o);
        int   oi = __shfl_xor_sync(0xFFFFFFFFu, bi, o);
        if (ov < bv || (ov == bv && oi < bi)) { bv = ov; bi = oi; }
    }
    if (!lane) { sv[wid] = bv; si[wid] = bi; }
    __syncthreads();
    int nw = blockDim.x >> 5;
    if (wid == 0) {
        float xv = (lane < nw) ? sv[lane] : 3e38f;
        int   xi = (lane < nw) ? si[lane] : 0x7FFFFFFF;
#pragma unroll
        for (int o = 16; o; o >>= 1) {
            float ov = __shfl_xor_sync(0xFFFFFFFFu, xv, o);
            int   oi = __shfl_xor_sync(0xFFFFFFFFu, xi, o);
            if (ov < xv || (ov == xv && oi < xi)) { xv = ov; xi = oi; }
        }
        if (!lane) { sv[0] = xv; si[0] = xi; }
    }
    __syncthreads();
    bv = sv[0]; bi = si[0];
    __syncthreads();
}

__device__ __forceinline__ void ldsm4(uint32_t addr, uint32_t& r0, uint32_t& r1,
                                      uint32_t& r2, uint32_t& r3) {
    asm volatile("ldmatrix.sync.aligned.m8n8.x4.shared.b16 {%0,%1,%2,%3}, [%4];"
                 : "=r"(r0), "=r"(r1), "=r"(r2), "=r"(r3) : "r"(addr));
}
__device__ __forceinline__ void ldsm2(uint32_t addr, uint32_t& r0, uint32_t& r1) {
    asm volatile("ldmatrix.sync.aligned.m8n8.x2.shared.b16 {%0,%1}, [%2];"
                 : "=r"(r0), "=r"(r1) : "r"(addr));
}
__device__ __forceinline__ void mma16816(float& c0, float& c1, float& c2, float& c3,
                                         uint32_t a0, uint32_t a1, uint32_t a2, uint32_t a3,
                                         uint32_t b0, uint32_t b1) {
    asm volatile("mma.sync.aligned.m16n8k16.row.col.f32.bf16.bf16.f32 "
                 "{%0,%1,%2,%3}, {%4,%5,%6,%7}, {%8,%9}, {%0,%1,%2,%3};"
                 : "+f"(c0), "+f"(c1), "+f"(c2), "+f"(c3)
                 : "r"(a0), "r"(a1), "r"(a2), "r"(a3), "r"(b0), "r"(b1));
}

__device__ __forceinline__ const float* srow(int i, int sp,
                                             const float* __restrict__ tok,
                                             const float* __restrict__ s_in) {
    int d = ((i - sp) % SSZ + SSZ) % SSZ;
    if (d < KPROM) return tok + (size_t)g_top[d] * DIM;
    return s_in + (size_t)i * DIM;
}

// ------------- kernels -------------

// stream A: lmean | toknorm (+flag init, +g_mean zero)
__global__ void __launch_bounds__(256) k_streamA(
    const float* __restrict__ tok, const float* __restrict__ l_in,
    float* __restrict__ out_l)
{
    int b = blockIdx.x, t = threadIdx.x;
    if (b == 0 && t == 0) { g_npairs = 0; g_intmax = 0ull; }

    if (b < NB_LMEAN) {
        int c  = (b & 3) * 256 + t;
        int rc = b >> 2;
        int r0 = rc * (LSZ / NLCHUNK);   // 16 rows
        float s = 0.f;
#pragma unroll
        for (int r = r0; r < r0 + (LSZ / NLCHUNK); r++) {
            float v = l_in[(size_t)r * DIM + c];
            out_l[(size_t)r * DIM + c] = v;
            s += v;
        }
        g_lpart[(size_t)rc * DIM + c] = s;
    } else {
        int tb = b - NB_LMEAN;
        if (tb < 4) g_mean[tb * 256 + t] = 0.f;   // zero for lred atomics (lred waits on evA)
        int w = (tb * 256 + t) >> 5;
        int lane = t & 31;
        const float4* p = (const float4*)(tok + (size_t)w * DIM);
        float s = 0.f;
#pragma unroll
        for (int k = 0; k < 8; k++) { float4 v = p[lane + 32 * k]; s += dot4(v, v); }
        s = wsum(s);
        if (!lane) g_norms[w] = s;
    }
}

// stream B: mprep(+out_m write) | s/mu/lu copies
__global__ void __launch_bounds__(256) k_streamB(
    const float* __restrict__ m,
    const float4* __restrict__ s_in4, float4* __restrict__ out_s4,
    float4* __restrict__ out_m4,
    const float4* __restrict__ mu4, float4* __restrict__ out_mu4,
    const float4* __restrict__ lu4, float4* __restrict__ out_lu4)
{
    int b = blockIdx.x, t = threadIdx.x;
    if (b < NB_MPREP) {
        int w = (b * 256 + t) >> 5;
        int lane = t & 31;
        const float4* mr = (const float4*)(m + (size_t)w * DIM);
        float4* mo = (float4*)((float*)out_m4 + (size_t)w * DIM);
        float n2 = 0.f;
        float4 vv[8];
#pragma unroll
        for (int k = 0; k < 8; k++) {
            vv[k] = mr[lane + 32 * k];
            n2 += dot4(vv[k], vv[k]);
        }
#pragma unroll
        for (int k = 0; k < 8; k++) mo[lane + 32 * k] = vv[k];
        n2 = wsum(n2);
        float sp2 = (lane < 16) ? dot4(vv[0], vv[0]) : 0.f;
        sp2 = wsum(sp2);
        float rinv = rsqrtf(n2);
        if (lane < 16) {
            __nv_bfloat162 lo = __floats2bfloat162_rn(vv[0].x * rinv, vv[0].y * rinv);
            __nv_bfloat162 hi = __floats2bfloat162_rn(vv[0].z * rinv, vv[0].w * rinv);
            __nv_bfloat162* dst = (__nv_bfloat162*)(g_Pb + (size_t)w * PD + lane * 4);
            dst[0] = lo;
            dst[1] = hi;
        }
        if (!lane) {
            g_mn2[w] = n2;
            g_res[w] = sqrtf(fmaxf(0.f, 1.f - sp2 * rinv * rinv));
        }
    } else {
        int cb = b - NB_MPREP;
        const int nS = SSZ * DIM / 4, nMu = MSZ / 4, nLu = LSZ / 4;
        int i = cb * 256 + t;
        int stride = NB_COPY * 256;
        for (int k = i; k < nS; k += stride) out_s4[k] = s_in4[k];
        for (int k = i; k < nMu; k += stride) out_mu4[k] = mu4[k];
        for (int k = i; k < nLu; k += stride) out_lu4[k] = lu4[k];
    }
}

// Cauchy-Schwarz screen via bf16 tensor cores
__global__ void k_screen() {
    __shared__ __align__(16) __nv_bfloat16 sPi[TB * LDPB];
    __shared__ __align__(16) __nv_bfloat16 sPj[TB * LDPB];
    __shared__ float sri[TB], srj[TB];
    int kblk = blockIdx.x;
    int bi = (int)((sqrtf(8.f * (float)kblk + 1.f) - 1.f) * 0.5f);
    while ((bi + 1) * (bi + 2) / 2 <= kblk) bi++;
    while (bi * (bi + 1) / 2 > kblk) bi--;
    int bj = kblk - bi * (bi + 1) / 2;
    int i0 = bi * TB, j0 = bj * TB;
    int t = threadIdx.x, lane = t & 31, wid = t >> 5;

    for (int it = t; it < TB * 8; it += 256) {
        int r = it >> 3, c = it & 7;
        *(uint4*)&sPi[r * LDPB + c * 8] = *(const uint4*)&g_Pb[(size_t)(i0 + r) * PD + c * 8];
        *(uint4*)&sPj[r * LDPB + c * 8] = *(const uint4*)&g_Pb[(size_t)(j0 + r) * PD + c * 8];
    }
    if (t < TB) { sri[t] = g_res[i0 + t]; srj[t] = g_res[j0 + t]; }
    __syncthreads();

    int warp_r = wid >> 2, warp_c = wid & 3;
    int rbase = warp_r * 64, cbase = warp_c * 32;
    uint32_t smem_i = (uint32_t)__cvta_generic_to_shared(sPi);
    uint32_t smem_j = (uint32_t)__cvta_generic_to_shared(sPj);

    float acc[4][4][4];
#pragma unroll
    for (int mt = 0; mt < 4; mt++)
#pragma unroll
        for (int nt = 0; nt < 4; nt++)
#pragma unroll
            for (int r = 0; r < 4; r++) acc[mt][nt][r] = 0.f;

#pragma unroll
    for (int ks = 0; ks < 4; ks++) {
        uint32_t afr[4][4];
        uint32_t bfr[4][2];
#pragma unroll
        for (int mt = 0; mt < 4; mt++) {
            int row = rbase + mt * 16 + (lane & 15);
            int col = ks * 16 + ((lane >> 4) << 3);
            ldsm4(smem_i + (uint32_t)(row * LDPB + col) * 2u,
                  afr[mt][0], afr[mt][1], afr[mt][2], afr[mt][3]);
        }
#pragma unroll
        for (int nt = 0; nt < 4; nt++) {
            int row = cbase + nt * 8 + (lane & 7);
            int col = ks * 16 + (lane & 8);
            ldsm2(smem_j + (uint32_t)(row * LDPB + col) * 2u,
                  bfr[nt][0], bfr[nt][1]);
        }
#pragma unroll
        for (int mt = 0; mt < 4; mt++)
#pragma unroll
            for (int nt = 0; nt < 4; nt++)
                mma16816(acc[mt][nt][0], acc[mt][nt][1], acc[mt][nt][2], acc[mt][nt][3],
                         afr[mt][0], afr[mt][1], afr[mt][2], afr[mt][3],
                         bfr[nt][0], bfr[nt][1]);
    }

    int gr = lane >> 2, tig = lane & 3;
#pragma unroll
    for (int mt = 0; mt < 4; mt++) {
        int r0l = rbase + mt * 16 + gr;
#pragma unroll
        for (int nt = 0; nt < 4; nt++) {
            int c0l = cbase + nt * 8 + 2 * tig;
#pragma unroll
            for (int e = 0; e < 4; e++) {
                int rl = r0l + ((e >> 1) ? 8 : 0);
                int cl = c0l + (e & 1);
                int i = i0 + rl, j = j0 + cl;
                if (i > j) {
                    float bound = acc[mt][nt][e] + sri[rl] * srj[cl];
                    if (bound > SCREEN_T) {
                        int p = atomicAdd(&g_npairs, 1);
                        if (p < PAIR_CAP) { g_pairs[2 * p] = i; g_pairs[2 * p + 1] = j; }
                    }
                }
            }
        }
    }
}

__global__ void k_exactW(const float* __restrict__ m) {
    int t = threadIdx.x, lane = t & 31;
    int np = g_npairs;
    if (np <= PAIR_CAP) {
        int gw = (blockIdx.x * blockDim.x + t) >> 5;
        int nw = (gridDim.x * blockDim.x) >> 5;
        for (int p = gw; p < np; p += nw) {
            int i = g_pairs[2 * p], j = g_pairs[2 * p + 1];
            const float4* a = (const float4*)(m + (size_t)i * DIM);
            const float4* b = (const float4*)(m + (size_t)j * DIM);
            float s = 0.f;
#pragma unroll
            for (int k = 0; k < 8; k++) s += dot4(a[lane + 32 * k], b[lane + 32 * k]);
            s = wsum(s);
            if (!lane) {
                float cosv = s * rsqrtf(g_mn2[i] * g_mn2[j]);
                unsigned long long key =
                    ((unsigned long long)ordf(cosv) << 32) | (0xFFFFFFFFu - (unsigned)(i * MSZ + j));
                atomicMax(&g_intmax, key);
            }
        }
    } else {
        __shared__ unsigned long long bk_;
        if (t == 0) bk_ = 0ull;
        __syncthreads();
        for (int i = blockIdx.x; i < MSZ; i += gridDim.x) {
            if (i == 0) continue;
            float bc = -2.f; int bf = 0;
            for (int j = t; j < i; j += 256) {
                float s = 0.f;
                const float* mi = m + (size_t)i * DIM;
                const float* mj = m + (size_t)j * DIM;
                for (int e = 0; e < DIM; e++) s += mi[e] * mj[e];
                float c = s * rsqrtf(g_mn2[i] * g_mn2[j]);
                if (c > bc) { bc = c; bf = i * MSZ + j; }
            }
            unsigned long long key = ((unsigned long long)ordf(bc) << 32) | (0xFFFFFFFFu - (unsigned)bf);
            atomicMax(&bk_, key);
        }
        __syncthreads();
        if (t == 0) atomicMax(&g_intmax, bk_);
    }
}

// parallel partial reduction: 256 blocks (64 kg x 4 cg), atomicAdd into g_mean
__global__ void k_lred() {
    int b = blockIdx.x, t = threadIdx.x;
    int kg = b >> 2, cg = b & 3;
    int c = cg * 256 + t;
    float s = 0.f;
#pragma unroll
    for (int k = kg * 8; k < kg * 8 + 8; k++) s += g_lpart[(size_t)k * DIM + c];
    atomicAdd(&g_mean[c], s / (float)LSZ);
}

// q = wq @ mean + bq, 1 row/warp across 128 CTAs
__global__ void k_q(const float* __restrict__ wq, const float* __restrict__ bq) {
    int t = threadIdx.x, lane = t & 31, w = t >> 5;
    int j = blockIdx.x * 8 + w;
    const float4* mr = (const float4*)g_mean;
    const float4* wr = (const float4*)(wq + (size_t)j * DIM);
    float acc = 0.f;
#pragma unroll
    for (int k = 0; k < 8; k++) acc += dot4(wr[lane + 32 * k], mr[lane + 32 * k]);
    acc = wsum(acc);
    if (!lane) g_q[j] = acc + bq[j];
}

__global__ void k_v1(const float* __restrict__ wk) {
    int c  = blockIdx.x * 256 + threadIdx.x;
    int r0 = blockIdx.y * (DIM / NVCHUNK);
    float s = 0.f;
#pragma unroll
    for (int r = r0; r < r0 + (DIM / NVCHUNK); r++)
        s += g_q[r] * wk[(size_t)r * DIM + c];
    g_vpart[blockIdx.y * DIM + c] = s;
}

// single-block top-128: 3-pass byte radix select
__global__ void k_topk() {
    __shared__ int   hist[256];
    __shared__ float sval[COLLECT_CAP];
    __shared__ int   sidx[COLLECT_CAP];
    __shared__ int   s_cnt;
    __shared__ unsigned s_pref;
    __shared__ int   s_kneed;
    __shared__ float wv[32]; __shared__ int wi[32];
    int t = threadIdx.x;

    if (t == 0) { s_pref = 0; s_kneed = KPROM; }
    for (int pass = 0; pass < 3; pass++) {
        int shift = 24 - 8 * pass;
        if (t < 256) hist[t] = 0;
        __syncthreads();
        unsigned pref = s_pref;
        for (int i = t; i < CANDN; i += 1024) {
            unsigned key = ordf(g_norms[i]);
            if ((key >> (shift + 8)) == pref)
                atomicAdd(&hist[(key >> shift) & 255u], 1);
        }
        __syncthreads();
        if (t == 0) {
            int kneed = s_kneed, cum = 0, b = 255;
            for (; b >= 0; b--) {
                cum += hist[b];
                if (cum >= kneed) break;
            }
            if (b < 0) b = 0;
            s_kneed = kneed - (cum - hist[b]);
            s_pref = (s_pref << 8) | (unsigned)b;
        }
        __syncthreads();
    }
    unsigned P24 = s_pref;
    if (t == 0) s_cnt = 0;
    __syncthreads();
    for (int i = t; i < CANDN; i += 1024) {
        float v = g_norms[i];
        if ((ordf(v) >> 8) >= P24) {
            int p = atomicAdd(&s_cnt, 1);
            if (p < COLLECT_CAP) { sval[p] = v; sidx[p] = i; }
        }
    }
    __syncthreads();
    int M = s_cnt;
    if (M <= COLLECT_CAP) {
        for (int s = t; s < M; s += 1024) {
            float v = sval[s]; int id = sidx[s]; int r = 0;
            for (int f = 0; f < M; f++) {
                float vf = sval[f]; int idf = sidx[f];
                r += (vf > v) || (vf == v && idf < id);
            }
            if (r < KPROM) g_top[r] = id;
        }
    } else {
        for (int it = 0; it < KPROM; it++) {
            float bv = -3e38f; int bi = 0x7FFFFFFF;
            for (int i = t; i < CANDN; i += 1024) {
                float v = g_norms[i];
                if (v > bv || (v == bv && i < bi)) { bv = v; bi = i; }
            }
            bargmax(bv, bi, wv, wi);
            if (t == 0) { g_top[it] = bi; g_norms[bi] = -3e38f; }
            __syncthreads();
        }
    }
}

__global__ void k_scatter(const float* __restrict__ tok, const int* __restrict__ sptr,
                          float* __restrict__ out_s) {
    int j = blockIdx.x;
    int p = ((sptr[0] + j) % SSZ + SSZ) % SSZ;
    int src = g_top[j];
    ((float4*)(out_s + (size_t)p * DIM))[threadIdx.x] =
        ((const float4*)(tok + (size_t)src * DIM))[threadIdx.x];
}

__global__ void k_scores(const float* __restrict__ tok, const float* __restrict__ s_in,
                         const int* __restrict__ sptr) {
    __shared__ __align__(16) float sv[DIM];
    int t = threadIdx.x;                 // 1024
    {
        float s = 0.f;
#pragma unroll 8
        for (int k = 0; k < NVCHUNK; k++) s += g_vpart[k * DIM + t];
        sv[t] = s;
    }
    __syncthreads();
    int lane = t & 31, w = t >> 5;
    int sp = sptr[0];
    const float4* vr = (const float4*)sv;
    int i = blockIdx.x * 32 + w;
    const float4* sr = (const float4*)srow(i, sp, tok, s_in);
    float s = 0.f;
#pragma unroll
    for (int k = 0; k < 8; k++) s += dot4(sr[lane + 32 * k], vr[lane + 32 * k]);
    s = wsum(s);
    if (!lane) g_scores[i] = s;
}

__global__ void k_msims(const float* __restrict__ m, const float* __restrict__ tok,
                        const float* __restrict__ s_in, const int* __restrict__ sptr) {
    __shared__ __align__(16) float sc[DIM];
    __shared__ float sv_[32]; __shared__ int si_[32]; __shared__ float sb[32];
    int t = threadIdx.x;                 // 256
    float bv = -3e38f; int bi = 0x7FFFFFFF;
    for (int i = t; i < SSZ; i += 256) {
        float v = g_scores[i];
        if (v > bv || (v == bv && i < bi)) { bv = v; bi = i; }
    }
    bargmax(bv, bi, sv_, si_);
    int best = bi;
    int sp = sptr[0];
    const float* src = srow(best, sp, tok, s_in);
    for (int c = t; c < DIM; c += 256) sc[c] = src[c];
    __syncthreads();
    float n2p = 0.f;
    for (int c = t; c < DIM; c += 256) n2p += sc[c] * sc[c];
    float n2 = bsum(n2p, sb);
    if (blockIdx.x == 0) {
        for (int c = t; c < DIM; c += 256) g_cand[c] = sc[c];
        if (t == 0) g_candn2 = n2;
    }
    float rc = rsqrtf(n2);
    int lane = t & 31;
    const float4* cr = (const float4*)sc;
    for (int w = (blockIdx.x * 256 + t) >> 5; w < MSZ; w += (gridDim.x * 256) >> 5) {
        const float4* mr = (const float4*)(m + (size_t)w * DIM);
        float dc = 0.f;
#pragma unroll
        for (int k = 0; k < 8; k++) dc += dot4(mr[lane + 32 * k], cr[lane + 32 * k]);
        dc = wsum(dc);
        if (!lane) g_sims[w] = dc * rsqrtf(g_mn2[w]) * rc;
    }
}

__global__ void k_decideltier(const float* __restrict__ m, const float* __restrict__ mu,
                              const float* __restrict__ l_in, const float* __restrict__ lu,
                              const int* __restrict__ sptr,
                              float* __restrict__ out_m, float* __restrict__ out_mu,
                              float* __restrict__ out_l, float* __restrict__ out_lu,
                              float* __restrict__ out_ptr) {
    __shared__ float sv[32]; __shared__ int si[32]; __shared__ float sb[32];
    __shared__ int s_any;
    int t = threadIdx.x;                 // 1024
    if (t == 0) s_any = 0;
    __syncthreads();
    float musum = 0.f, mn = 3e38f; int mni = 0x7FFFFFFF; int anyz = 0;
    for (int i = t; i < MSZ; i += 1024) {
        float u = mu[i];
        musum += u;
        if (u < mn) { mn = u; mni = i; }
        anyz |= (u == 0.f);
    }
    if (anyz) atomicOr(&s_any, 1);
    float mu_mean = bsum(musum, sb) / (float)MSZ;
    bargmin(mn, mni, sv, si);
    int li = mni;
    __syncthreads();
    int any0 = s_any;
    float smax = -3e38f; int smi = 0x7FFFFFFF;
    for (int i = t; i < MSZ; i += 1024) {
        float s = g_sims[i];
        if (s > smax || (s == smax && i < smi)) { smax = s; smi = i; }
    }
    bargmax(smax, smi, sv, si);
    int msi = smi; float simcand = smax;
    float cosint = -2.f; int i1 = 0, i2 = 0;
    if (g_npairs > 0) {
        unsigned long long kk = g_intmax;
        cosint = deordf((unsigned)(kk >> 32));
        unsigned fl = 0xFFFFFFFFu - (unsigned)(kk & 0xFFFFFFFFu);
        i1 = fl / MSZ; i2 = fl % MSZ;
    }
    if (any0) {
        out_m[(size_t)li * DIM + t] = g_cand[t];
        if (t == 0) out_mu[li] = mu_mean + 1e-5f;
    } else if (simcand > MERGE_T) {
        float merged = (m[(size_t)msi * DIM + t] + g_cand[t]) * 0.5f;
        float n2 = bsum(merged * merged, sb);
        float dn = fmaxf(sqrtf(n2), 1e-12f);
        out_m[(size_t)msi * DIM + t] = merged / dn;
        if (t == 0) out_mu[msi] = (mu[msi] + mu_mean) * 0.5f;
    } else if (cosint > MERGE_T) {
        float merged = (m[(size_t)i1 * DIM + t] + m[(size_t)i2 * DIM + t]) * 0.5f;
        float n2 = bsum(merged * merged, sb);
        float dn = fmaxf(sqrtf(n2), 1e-12f);
        out_m[(size_t)i1 * DIM + t] = merged / dn;
        out_m[(size_t)i2 * DIM + t] = g_cand[t];
        if (t == 0) {
            float nu1 = (mu[i1] + mu[i2]) * 0.5f;
            out_mu[i1] = nu1;
            float mean2 = mu_mean + (nu1 - mu[i1]) / (float)MSZ;
            out_mu[i2] = mean2 + 1e-5f;
        }
    } else {
        if (g_candn2 > g_mn2[li]) {
            out_m[(size_t)li * DIM + t] = g_cand[t];
            if (t == 0) out_mu[li] = mu_mean + 1e-5f;
        }
    }
    __syncthreads();

    float mx = -3e38f; int mxi = 0x7FFFFFFF;
    for (int i = t; i < MSZ; i += 1024) {
        float u = out_mu[i];
        if (u > mx || (u == mx && i < mxi)) { mx = u; mxi = i; }
    }
    bargmax(mx, mxi, sv, si);
    int mi = mxi;
    float lsum = 0.f, lmn = 3e38f; int lmni = 0x7FFFFFFF;
    for (int i = t; i < LSZ; i += 1024) {
        float u = lu[i];
        lsum += u;
        if (u < lmn) { lmn = u; lmni = i; }
    }
    float ltot = bsum(lsum, sb);
    bargmin(lmn, lmni, sv, si);
    int lj = lmni;
    out_l[(size_t)lj * DIM + t] =
        0.9f * l_in[(size_t)lj * DIM + t] + 0.1f * out_m[(size_t)mi * DIM + t];
    if (t == 0) {
        out_lu[lj] = ltot / (float)LSZ;
        out_ptr[0] = (float)(((sptr[0] + KPROM) % SSZ + SSZ) % SSZ);
    }
}

// ------------- host -------------
extern "C" void kernel_launch(void* const* d_in, const int* in_sizes, int n_in,
                              void* d_out, int out_size) {
    const float* tok  = (const float*)d_in[0];
    const float* s_in = (const float*)d_in[1];
    const float* m_in = (const float*)d_in[2];
    const float* l_in = (const float*)d_in[3];
    const float* mu   = (const float*)d_in[4];
    const float* lu   = (const float*)d_in[5];
    const float* wq   = (const float*)d_in[6];
    const float* bq   = (const float*)d_in[7];
    const float* wk   = (const float*)d_in[8];
    const int*   sptr = (const int*)d_in[10];

    float* out    = (float*)d_out;
    float* out_s  = out;
    float* out_m  = out_s + (size_t)SSZ * DIM;
    float* out_l  = out_m + (size_t)MSZ * DIM;
    float* out_mu = out_l + (size_t)LSZ * DIM;
    float* out_lu = out_mu + MSZ;
    float* out_ptr = out_lu + LSZ;

    static cudaStream_t sA = 0, sB = 0, sC = 0;
    static cudaEvent_t evA0 = 0, evB0 = 0, evTopk = 0, evA = 0, evB = 0, evC = 0;
    if (!sA) {
        cudaStreamCreateWithFlags(&sA, cudaStreamNonBlocking);
        cudaStreamCreateWithFlags(&sB, cudaStreamNonBlocking);
        cudaStreamCreateWithFlags(&sC, cudaStreamNonBlocking);
        cudaEventCreateWithFlags(&evA0, cudaEventDisableTiming);
        cudaEventCreateWithFlags(&evB0, cudaEventDisableTiming);
        cudaEventCreateWithFlags(&evTopk, cudaEventDisableTiming);
        cudaEventCreateWithFlags(&evA, cudaEventDisableTiming);
        cudaEventCreateWithFlags(&evB, cudaEventDisableTiming);
        cudaEventCreateWithFlags(&evC, cudaEventDisableTiming);
    }

    // stage A: lmean + toknorm (feeds B-chain & topk)
    k_streamA<<<NB_A, 256>>>(tok, l_in, out_l);
    cudaEventRecord(evA0, 0);

    // stage B: mprep + copies (B-chain & topk hide under this)
    k_streamB<<<NB_B, 256>>>(m_in,
                             (const float4*)s_in, (float4*)out_s,
                             (float4*)out_m,
                             (const float4*)mu, (float4*)out_mu,
                             (const float4*)lu, (float4*)out_lu);
    cudaEventRecord(evB0, 0);

    // stream 0: screen -> exactW (after mprep)
    k_screen<<<NTRI, 256>>>();
    k_exactW<<<64, 256>>>(m_in);

    // branch B (overlaps streamB): lred -> q -> v1
    cudaStreamWaitEvent(sB, evA0, 0);
    k_lred<<<256, 256, 0, sB>>>();
    k_q<<<128, 256, 0, sB>>>(wq, bq);
    k_v1<<<dim3(DIM / 256, NVCHUNK), 256, 0, sB>>>(wk);
    cudaEventRecord(evB, sB);

    // branch C (overlaps streamB): topk, then scores -> msims
    cudaStreamWaitEvent(sC, evA0, 0);
    k_topk<<<1, 1024, 0, sC>>>();
    cudaEventRecord(evTopk, sC);
    cudaStreamWaitEvent(sC, evB, 0);
    k_scores<<<16, 1024, 0, sC>>>(tok, s_in, sptr);
    cudaStreamWaitEvent(sC, evB0, 0);
    k_msims<<<256, 256, 0, sC>>>(m_in, tok, s_in, sptr);
    cudaEventRecord(evC, sC);

    // branch A: scatter (needs topk + out_s copy from streamB)
    cudaStreamWaitEvent(sA, evTopk, 0);
    cudaStreamWaitEvent(sA, evB0, 0);
    k_scatter<<<KPROM, 256, 0, sA>>>(tok, sptr, out_s);
    cudaEventRecord(evA, sA);

    // join + tail
    cudaStreamWaitEvent(0, evC, 0);
    cudaStreamWaitEvent(0, evA, 0);
    k_decideltier<<<1, 1024>>>(m_in, mu, l_in, lu, sptr,
                               out_m, out_mu, out_l, out_lu, out_ptr);
}